// round 11
// baseline (speedup 1.0000x reference)
#include <cuda_runtime.h>
#include <cuda_fp16.h>
#include <cstdint>

#define TILE_Z 32
#define NTH    256
#define NITER  4

#define C000f 0.7071067811865476f
#define C110f 0.4082482904638631f
#define C011f 0.7071067811865476f
#define C101f 0.7071067811865476f

// B fragments, fp16-packed, 0.125-scaled: [wsel(2)][kk(4)][n(128)][tig(4)] uint2
__device__ uint2 g_wt[4096];
// Folded tp_w: [0]=C000*wA, [64]=C110*wD, [128]=C011*wB, [192]=C101*wC
__device__ float g_tpw[256];

__device__ __forceinline__ uint32_t smem_u32(const void* p) {
    uint32_t a;
    asm("{ .reg .u64 t; cvta.to.shared.u64 t, %1; cvt.u32.u64 %0, t; }" : "=r"(a) : "l"(p));
    return a;
}
__device__ __forceinline__ uint32_t h2u(float a, float b) {
    __half2 h = __floats2half2_rn(a, b);
    return *reinterpret_cast<uint32_t*>(&h);
}
__device__ __forceinline__ void ldsm_x4(uint32_t* r, uint32_t addr) {
    asm volatile("ldmatrix.sync.aligned.m8n8.x4.shared.b16 {%0,%1,%2,%3}, [%4];"
        : "=r"(r[0]), "=r"(r[1]), "=r"(r[2]), "=r"(r[3]) : "r"(addr));
}
__device__ __forceinline__ void mma_f16(float* c, const uint32_t* a, uint2 b) {
    asm volatile("mma.sync.aligned.m16n8k16.row.col.f32.f16.f16.f32 "
        "{%0,%1,%2,%3}, {%4,%5,%6,%7}, {%8,%9}, {%0,%1,%2,%3};"
        : "+f"(c[0]), "+f"(c[1]), "+f"(c[2]), "+f"(c[3])
        : "r"(a[0]), "r"(a[1]), "r"(a[2]), "r"(a[3]), "r"(b.x), "r"(b.y));
}

// 1D bulk async copy smem -> gmem (sm_90+, no tensor map needed)
#define BULK_S2G(gptr, saddr, bytes) \
    asm volatile("cp.async.bulk.global.shared::cta.bulk_group [%0], [%1], %2;" \
        :: "l"(gptr), "r"((uint32_t)(saddr)), "r"((uint32_t)(bytes)) : "memory")
#define BULK_COMMIT()      asm volatile("cp.async.bulk.commit_group;" ::: "memory")
#define BULK_WAIT_READ(n)  asm volatile("cp.async.bulk.wait_group.read %0;" :: "n"(n) : "memory")
#define BULK_WAIT(n)       asm volatile("cp.async.bulk.wait_group %0;" :: "n"(n) : "memory")
#define FENCE_PROXY_ASYNC() asm volatile("fence.proxy.async.shared::cta;" ::: "memory")

// ---------------- pack kernel ----------------
__global__ void pack_kernel(const float* __restrict__ tp_w,
                            const float* __restrict__ w0,
                            const float* __restrict__ w1) {
    int t = blockIdx.x * blockDim.x + threadIdx.x;
    if (t < 4096) {
        int tig  = t & 3;
        int n    = (t >> 2) & 127;
        int kk   = (t >> 9) & 3;
        int wsel = t >> 11;
        const float* w = wsel ? w1 : w0;
        int K0 = kk * 16 + 2 * tig;
        uint2 v;
        v.x = h2u(w[K0 * 128 + n] * 0.125f,       w[(K0 + 1) * 128 + n] * 0.125f);
        v.y = h2u(w[(K0 + 8) * 128 + n] * 0.125f, w[(K0 + 9) * 128 + n] * 0.125f);
        g_wt[t] = v;
    } else if (t < 4096 + 64) {
        int u = t - 4096;
        g_tpw[u]       = C000f * tp_w[u];
        g_tpw[64 + u]  = C110f * tp_w[192 + u];
        g_tpw[128 + u] = C011f * tp_w[64 + u];
        g_tpw[192 + u] = C101f * tp_w[128 + u];
    }
}

// ---------------- main kernel ----------------
// Per-CTA dynamic smem:
//   A single buffer: half[128 rows][72] = 18432 B
//   stage double buffer: 2 x float[16][516] = 33024 B each
// Total 84480 B -> 2 CTAs/SM = 168960 B; ~59 KB L1D left (B stays cached).
#define A_ROW_H   72
#define A_BYTES   (128 * A_ROW_H * 2)        // 18432
#define STG_STRIDE 516
#define STG_BYTES (16 * STG_STRIDE * 4)      // 33024
#define STG_OFF   A_BYTES
#define DSM_BYTES (STG_OFF + 2 * STG_BYTES)  // 84480

// Phase 1: compute mids for one 32-row tile, pack half2, STS into A buffer.
__device__ __forceinline__ void phase1(__half* A, const float* __restrict__ x,
                                       const float* __restrict__ y, int z0,
                                       const float* s_tpw, int tid) {
    #pragma unroll
    for (int it = 0; it < (TILE_Z * 16) / NTH; it++) {
        int task = tid + NTH * it;        // 0..511
        int z = task >> 4;
        int q = task & 15;
        const float* xp = x + (size_t)(z0 + z) * 256;
        float4 X0 = *(const float4*)(xp + 4 * q);
        const float4* xq = (const float4*)(xp + 64 + 12 * q);
        float4 P0 = xq[0], P1 = xq[1], P2 = xq[2];
        float4 Y  = *(const float4*)(y + (size_t)(z0 + z) * 4);
        float y0v = Y.x, ya = Y.y, yb = Y.z, yc = Y.w;
        float4 tA = *(const float4*)(s_tpw + 4 * q);
        float4 tD = *(const float4*)(s_tpw + 64 + 4 * q);
        float4 tB = *(const float4*)(s_tpw + 128 + 4 * q);
        float4 tC = *(const float4*)(s_tpw + 192 + 4 * q);

        float x0a[4] = {X0.x, X0.y, X0.z, X0.w};
        float xaa[4] = {P0.x, P0.w, P1.z, P2.y};
        float xba[4] = {P0.y, P1.x, P1.w, P2.z};
        float xca[4] = {P0.z, P1.y, P2.x, P2.w};
        float tAa[4] = {tA.x, tA.y, tA.z, tA.w};
        float tDa[4] = {tD.x, tD.y, tD.z, tD.w};
        float tBa[4] = {tB.x, tB.y, tB.z, tB.w};
        float tCa[4] = {tC.x, tC.y, tC.z, tC.w};

        float m0[4], ma[4], mb[4], mc[4];
        #pragma unroll
        for (int j = 0; j < 4; j++) {
            m0[j] = tAa[j] * x0a[j] * y0v
                  + tDa[j] * (xaa[j] * ya + xba[j] * yb + xca[j] * yc);
            float tb = tBa[j] * x0a[j];
            float tc = tCa[j] * y0v;
            ma[j] = tb * ya + tc * xaa[j];
            mb[j] = tb * yb + tc * xba[j];
            mc[j] = tb * yc + tc * xca[j];
        }
        uint2 H0 = make_uint2(h2u(m0[0], m0[1]), h2u(m0[2], m0[3]));
        uint2 HA = make_uint2(h2u(ma[0], ma[1]), h2u(ma[2], ma[3]));
        uint2 HB = make_uint2(h2u(mb[0], mb[1]), h2u(mb[2], mb[3]));
        uint2 HC = make_uint2(h2u(mc[0], mc[1]), h2u(mc[2], mc[3]));

        __half* rp = A + (size_t)z * A_ROW_H + 4 * q;
        *(uint2*)(rp)                 = H0;   // rows  0..31  : ch0
        *(uint2*)(rp + 32 * A_ROW_H)  = HA;   // rows 32..63  : ch1
        *(uint2*)(rp + 64 * A_ROW_H)  = HB;   // rows 64..95  : ch2
        *(uint2*)(rp + 96 * A_ROW_H)  = HC;   // rows 96..127 : ch3
    }
}

// Stage a 16-row chunk (one m-tile): this warp's [8][4] acc slice.
__device__ __forceinline__ void stage_write16(float* stage, const float a[8][4],
                                              int mq, int nh, int gID, int tig) {
    float* r0 = stage + (size_t)gID * STG_STRIDE;
    float* r1 = r0 + 8 * STG_STRIDE;
    if (mq == 0) {
        #pragma unroll
        for (int nt = 0; nt < 8; nt++) {
            int col = nh * 64 + nt * 8 + 2 * tig;
            *(float2*)(r0 + col) = make_float2(a[nt][0], a[nt][1]);
            *(float2*)(r1 + col) = make_float2(a[nt][2], a[nt][3]);
        }
    } else {
        int k3 = mq - 1;
        #pragma unroll
        for (int nt = 0; nt < 8; nt++) {
            int n = nh * 64 + nt * 8 + 2 * tig;
            int o = 128 + 3 * n + k3;
            r0[o]     = a[nt][0];
            r0[o + 3] = a[nt][1];
            r1[o]     = a[nt][2];
            r1[o + 3] = a[nt][3];
        }
    }
}

__global__ void __launch_bounds__(NTH, 2)
tpmm_kernel(const float* __restrict__ x, const float* __restrict__ y,
            float* __restrict__ out) {
    extern __shared__ __align__(128) char dsm[];
    __shared__ float s_tpw[256];

    const int tid = threadIdx.x;
    if (tid < 256) s_tpw[tid] = g_tpw[tid];

    const int warp = tid >> 5;
    const int lane = tid & 31;
    const int gID  = lane >> 2;
    const int tig  = lane & 3;
    const int mq   = warp >> 1;   // 0..3 channel
    const int nh   = warp & 1;    // 0..1 N half

    float* stg[2] = { (float*)(dsm + STG_OFF), (float*)(dsm + STG_OFF + STG_BYTES) };
    const uint32_t stg_sm[2] = { smem_u32(stg[0]), smem_u32(stg[1]) };
    const uint2* wb = g_wt + (mq ? 2048 : 0) + nh * 256 + gID * 4 + tig;

    const int t0z = blockIdx.x * (NITER * TILE_Z);
    const bool issuer = (tid < 16);

    __syncthreads();   // s_tpw visible
    phase1((__half*)dsm, x, y, t0z, s_tpw, tid);

    const uint32_t a_base = smem_u32(dsm)
        + (uint32_t)((mq * 32 + ((lane >> 3) & 1) * 8 + (lane & 7)) * (A_ROW_H * 2))
        + (uint32_t)((lane >> 4) * 16);

    #pragma unroll
    for (int t = 0; t < NITER; t++) {
        const int z0 = t0z + t * TILE_Z;

        if (issuer) BULK_WAIT_READ(1);   // stg0 of prev tile free (no-op on t=0... grp order)
        __syncthreads();                  // bar1: A[t] visible, stg0 free

        float acc[2][8][4];
        #pragma unroll
        for (int mt = 0; mt < 2; mt++)
            #pragma unroll
            for (int nt = 0; nt < 8; nt++)
                #pragma unroll
                for (int j = 0; j < 4; j++) acc[mt][nt][j] = 0.f;

        #pragma unroll
        for (int kk = 0; kk < 4; kk++) {
            uint32_t afr[2][4];
            #pragma unroll
            for (int mt = 0; mt < 2; mt++)
                ldsm_x4(afr[mt], a_base + (uint32_t)(mt * 16 * A_ROW_H * 2 + kk * 32));
            uint2 bfr[8];
            #pragma unroll
            for (int nt = 0; nt < 8; nt++) bfr[nt] = wb[kk * 512 + nt * 32];
            #pragma unroll
            for (int mt = 0; mt < 2; mt++)
                #pragma unroll
                for (int nt = 0; nt < 8; nt++)
                    mma_f16(acc[mt][nt], afr[mt], bfr[nt]);
        }

        // ---- chunk 0: rows z0..z0+15 via stg0 ----
        stage_write16(stg[0], acc[0], mq, nh, gID, tig);
        __syncthreads();                  // bar2: stg0 staged; all ldsm of A done
        if (issuer) {
            FENCE_PROXY_ASYNC();
            BULK_S2G(out + (size_t)(z0 + tid) * 512,
                     stg_sm[0] + (uint32_t)tid * (STG_STRIDE * 4), 2048u);
            BULK_COMMIT();
            BULK_WAIT_READ(1);            // stg1 of prev tile free
        }

        // Overlapped phase 1 for next tile (single A buffer is safe after bar2).
        if (t + 1 < NITER)
            phase1((__half*)dsm, x, y, z0 + TILE_Z, s_tpw, tid);

        __syncthreads();                  // bar3: stg1 free confirmed to all
        // ---- chunk 1: rows z0+16..z0+31 via stg1 ----
        stage_write16(stg[1], acc[1], mq, nh, gID, tig);
        __syncthreads();                  // bar4: stg1 staged
        if (issuer) {
            FENCE_PROXY_ASYNC();
            BULK_S2G(out + (size_t)(z0 + 16 + tid) * 512,
                     stg_sm[1] + (uint32_t)tid * (STG_STRIDE * 4), 2048u);
            BULK_COMMIT();
        }
    }

    if (issuer) BULK_WAIT(0);   // drain all outstanding bulk stores
}

extern "C" void kernel_launch(void* const* d_in, const int* in_sizes, int n_in,
                              void* d_out, int out_size) {
    const float* x    = (const float*)d_in[0];
    const float* y    = (const float*)d_in[1];
    const float* tp_w = (const float*)d_in[2];
    const float* w0   = (const float*)d_in[3];
    const float* w1   = (const float*)d_in[4];
    float* out        = (float*)d_out;

    int Z = in_sizes[0] / 256;

    pack_kernel<<<(4096 + 64 + 255) / 256, 256>>>(tp_w, w0, w1);

    cudaFuncSetAttribute(tpmm_kernel,
                         cudaFuncAttributeMaxDynamicSharedMemorySize, DSM_BYTES);
    tpmm_kernel<<<Z / (TILE_Z * NITER), NTH, DSM_BYTES>>>(x, y, out);
}

// round 12
// speedup vs baseline: 1.4130x; 1.4130x over previous
#include <cuda_runtime.h>
#include <cuda_fp16.h>
#include <cstdint>

#define TILE_Z 32
#define NTH    256
#define NITER  4

#define C000f 0.7071067811865476f
#define C110f 0.4082482904638631f
#define C011f 0.7071067811865476f
#define C101f 0.7071067811865476f

// B fragments, fp16-packed, 0.125-scaled: [wsel(2)][kk(4)][n(128)][tig(4)] uint2
__device__ uint2 g_wt[4096];
// Folded tp_w: [0]=C000*wA, [64]=C110*wD, [128]=C011*wB, [192]=C101*wC
__device__ float g_tpw[256];

__device__ __forceinline__ uint32_t smem_u32(const void* p) {
    uint32_t a;
    asm("{ .reg .u64 t; cvta.to.shared.u64 t, %1; cvt.u32.u64 %0, t; }" : "=r"(a) : "l"(p));
    return a;
}
__device__ __forceinline__ uint32_t h2u(float a, float b) {
    __half2 h = __floats2half2_rn(a, b);
    return *reinterpret_cast<uint32_t*>(&h);
}
__device__ __forceinline__ void ldsm_x4(uint32_t* r, uint32_t addr) {
    asm volatile("ldmatrix.sync.aligned.m8n8.x4.shared.b16 {%0,%1,%2,%3}, [%4];"
        : "=r"(r[0]), "=r"(r[1]), "=r"(r[2]), "=r"(r[3]) : "r"(addr));
}
__device__ __forceinline__ void mma_f16(float* c, const uint32_t* a, uint2 b) {
    asm volatile("mma.sync.aligned.m16n8k16.row.col.f32.f16.f16.f32 "
        "{%0,%1,%2,%3}, {%4,%5,%6,%7}, {%8,%9}, {%0,%1,%2,%3};"
        : "+f"(c[0]), "+f"(c[1]), "+f"(c[2]), "+f"(c[3])
        : "r"(a[0]), "r"(a[1]), "r"(a[2]), "r"(a[3]), "r"(b.x), "r"(b.y));
}

// ---------------- pack kernel ----------------
__global__ void pack_kernel(const float* __restrict__ tp_w,
                            const float* __restrict__ w0,
                            const float* __restrict__ w1) {
    int t = blockIdx.x * blockDim.x + threadIdx.x;
    if (t < 4096) {
        int tig  = t & 3;
        int n    = (t >> 2) & 127;
        int kk   = (t >> 9) & 3;
        int wsel = t >> 11;
        const float* w = wsel ? w1 : w0;
        int K0 = kk * 16 + 2 * tig;
        uint2 v;
        v.x = h2u(w[K0 * 128 + n] * 0.125f,       w[(K0 + 1) * 128 + n] * 0.125f);
        v.y = h2u(w[(K0 + 8) * 128 + n] * 0.125f, w[(K0 + 9) * 128 + n] * 0.125f);
        g_wt[t] = v;
    } else if (t < 4096 + 64) {
        int u = t - 4096;
        g_tpw[u]       = C000f * tp_w[u];
        g_tpw[64 + u]  = C110f * tp_w[192 + u];
        g_tpw[128 + u] = C011f * tp_w[64 + u];
        g_tpw[192 + u] = C101f * tp_w[128 + u];
    }
}

// ---------------- main kernel ----------------
// Per-CTA dynamic smem:
//   A double buffer: 2 x half[128 rows][72] (18432 B each) -> 36864
//   stage double buffer (interleaved cols only): 2 x float[8][396] (12672 B) -> 25344
// Total 62208 B -> 2 CTAs/SM = 124416 B; ~104 KB L1D left (B stays cached).
#define A_ROW_H   72
#define A_BYTES   (128 * A_ROW_H * 2)        // 18432
#define STG_STRIDE 396
#define STG_BYTES (8 * STG_STRIDE * 4)       // 12672
#define STG_OFF   (2 * A_BYTES)              // 36864
#define DSM_BYTES (STG_OFF + 2 * STG_BYTES)  // 62208

// Phase 1: compute mids for one 32-row tile, pack half2, STS into A buffer.
__device__ __forceinline__ void phase1(__half* A, const float* __restrict__ x,
                                       const float* __restrict__ y, int z0,
                                       const float* s_tpw, int tid) {
    #pragma unroll
    for (int it = 0; it < (TILE_Z * 16) / NTH; it++) {
        int task = tid + NTH * it;        // 0..511
        int z = task >> 4;
        int q = task & 15;
        const float* xp = x + (size_t)(z0 + z) * 256;
        float4 X0 = *(const float4*)(xp + 4 * q);
        const float4* xq = (const float4*)(xp + 64 + 12 * q);
        float4 P0 = xq[0], P1 = xq[1], P2 = xq[2];
        float4 Y  = *(const float4*)(y + (size_t)(z0 + z) * 4);
        float y0v = Y.x, ya = Y.y, yb = Y.z, yc = Y.w;
        float4 tA = *(const float4*)(s_tpw + 4 * q);
        float4 tD = *(const float4*)(s_tpw + 64 + 4 * q);
        float4 tB = *(const float4*)(s_tpw + 128 + 4 * q);
        float4 tC = *(const float4*)(s_tpw + 192 + 4 * q);

        float x0a[4] = {X0.x, X0.y, X0.z, X0.w};
        float xaa[4] = {P0.x, P0.w, P1.z, P2.y};
        float xba[4] = {P0.y, P1.x, P1.w, P2.z};
        float xca[4] = {P0.z, P1.y, P2.x, P2.w};
        float tAa[4] = {tA.x, tA.y, tA.z, tA.w};
        float tDa[4] = {tD.x, tD.y, tD.z, tD.w};
        float tBa[4] = {tB.x, tB.y, tB.z, tB.w};
        float tCa[4] = {tC.x, tC.y, tC.z, tC.w};

        float m0[4], ma[4], mb[4], mc[4];
        #pragma unroll
        for (int j = 0; j < 4; j++) {
            m0[j] = tAa[j] * x0a[j] * y0v
                  + tDa[j] * (xaa[j] * ya + xba[j] * yb + xca[j] * yc);
            float tb = tBa[j] * x0a[j];
            float tc = tCa[j] * y0v;
            ma[j] = tb * ya + tc * xaa[j];
            mb[j] = tb * yb + tc * xba[j];
            mc[j] = tb * yc + tc * xca[j];
        }
        uint2 H0 = make_uint2(h2u(m0[0], m0[1]), h2u(m0[2], m0[3]));
        uint2 HA = make_uint2(h2u(ma[0], ma[1]), h2u(ma[2], ma[3]));
        uint2 HB = make_uint2(h2u(mb[0], mb[1]), h2u(mb[2], mb[3]));
        uint2 HC = make_uint2(h2u(mc[0], mc[1]), h2u(mc[2], mc[3]));

        __half* rp = A + (size_t)z * A_ROW_H + 4 * q;
        *(uint2*)(rp)                 = H0;   // rows  0..31  : ch0
        *(uint2*)(rp + 32 * A_ROW_H)  = HA;   // rows 32..63  : ch1
        *(uint2*)(rp + 64 * A_ROW_H)  = HB;   // rows 64..95  : ch2
        *(uint2*)(rp + 96 * A_ROW_H)  = HC;   // rows 96..127 : ch3
    }
}

// ch0 (cols 0..127): direct, sector-aligned STG for an 8-row chunk.
__device__ __forceinline__ void ch0_store8(float* __restrict__ out, int zbase,
                                           const float a[8][4], int h2,
                                           int nh, int gID, int tig) {
    float* o0 = out + (size_t)(zbase + gID) * 512 + nh * 64 + 2 * tig;
    #pragma unroll
    for (int nt = 0; nt < 8; nt++)
        *(float2*)(o0 + nt * 8) = make_float2(a[nt][h2], a[nt][h2 + 1]);
}

// Interleaved channels (stage col = 3n + k3, representing out col 128+3n+k3).
__device__ __forceinline__ void stage_write8i(float* stage, const float a[8][4], int h2,
                                              int k3, int nh, int gID, int tig) {
    float* r0 = stage + (size_t)gID * STG_STRIDE;
    #pragma unroll
    for (int nt = 0; nt < 8; nt++) {
        int n = nh * 64 + nt * 8 + 2 * tig;
        int o = 3 * n + k3;
        r0[o]     = a[nt][h2];
        r0[o + 3] = a[nt][h2 + 1];
    }
}

// Coalesced float4 copy-out of the 384 interleaved cols for an 8-row chunk.
__device__ __forceinline__ void copyout8i(float* __restrict__ out, int zbase,
                                          const float* stage, int tid) {
    #pragma unroll
    for (int j = 0; j < 3; j++) {       // 8 rows x 96 float4 = 768 = 3 x 256
        int i = tid + NTH * j;
        int s = i / 96;
        int c = i % 96;
        float4 v = *(const float4*)(stage + (size_t)s * STG_STRIDE + 4 * c);
        *(float4*)(out + (size_t)(zbase + s) * 512 + 128 + 4 * c) = v;
    }
}

__global__ void __launch_bounds__(NTH, 2)
tpmm_kernel(const float* __restrict__ x, const float* __restrict__ y,
            float* __restrict__ out) {
    extern __shared__ __align__(128) char dsm[];
    __shared__ float s_tpw[256];

    const int tid = threadIdx.x;
    if (tid < 256) s_tpw[tid] = g_tpw[tid];

    const int warp = tid >> 5;
    const int lane = tid & 31;
    const int gID  = lane >> 2;
    const int tig  = lane & 3;
    const int mq   = warp >> 1;   // 0..3 channel
    const int nh   = warp & 1;    // 0..1 N half

    float* stg0 = (float*)(dsm + STG_OFF);
    float* stg1 = (float*)(dsm + STG_OFF + STG_BYTES);
    const uint2* wb = g_wt + (mq ? 2048 : 0) + nh * 256 + gID * 4 + tig;

    const int t0z = blockIdx.x * (NITER * TILE_Z);

    __syncthreads();   // s_tpw visible
    phase1((__half*)dsm, x, y, t0z, s_tpw, tid);

    #pragma unroll
    for (int t = 0; t < NITER; t++) {
        const int z0 = t0z + t * TILE_Z;
        __syncthreads();   // A[t&1] ready; prev tile's last copy-out done

        const uint32_t a_base = smem_u32(dsm) + (uint32_t)((t & 1) * A_BYTES)
            + (uint32_t)((mq * 32 + ((lane >> 3) & 1) * 8 + (lane & 7)) * (A_ROW_H * 2))
            + (uint32_t)((lane >> 4) * 16);

        float acc[2][8][4];
        #pragma unroll
        for (int mt = 0; mt < 2; mt++)
            #pragma unroll
            for (int nt = 0; nt < 8; nt++)
                #pragma unroll
                for (int j = 0; j < 4; j++) acc[mt][nt][j] = 0.f;

        #pragma unroll
        for (int kk = 0; kk < 4; kk++) {
            uint32_t afr[2][4];
            #pragma unroll
            for (int mt = 0; mt < 2; mt++)
                ldsm_x4(afr[mt], a_base + (uint32_t)(mt * 16 * A_ROW_H * 2 + kk * 32));
            uint2 bfr[8];
            #pragma unroll
            for (int nt = 0; nt < 8; nt++) bfr[nt] = wb[kk * 512 + nt * 32];
            #pragma unroll
            for (int mt = 0; mt < 2; mt++)
                #pragma unroll
                for (int nt = 0; nt < 8; nt++)
                    mma_f16(acc[mt][nt], afr[mt], bfr[nt]);
        }

        // ---- Epilogue: 4 chunks of 8 rows; ch0 direct STG, ch1..3 staged. ----
        // chunk 0 (mt 0, h2 0) -> stg0
        if (mq == 0) ch0_store8(out, z0, acc[0], 0, nh, gID, tig);
        else         stage_write8i(stg0, acc[0], 0, mq - 1, nh, gID, tig);
        __syncthreads();
        copyout8i(out, z0, stg0, tid);
        // chunk 1 (mt 0, h2 2) -> stg1
        if (mq == 0) ch0_store8(out, z0 + 8, acc[0], 2, nh, gID, tig);
        else         stage_write8i(stg1, acc[0], 2, mq - 1, nh, gID, tig);
        __syncthreads();
        copyout8i(out, z0 + 8, stg1, tid);

        // acc[0] dead -> overlapped phase 1 for next tile.
        if (t + 1 < NITER)
            phase1((__half*)(dsm + ((t + 1) & 1) * A_BYTES), x, y, z0 + TILE_Z, s_tpw, tid);

        // chunk 2 (mt 1, h2 0) -> stg0
        if (mq == 0) ch0_store8(out, z0 + 16, acc[1], 0, nh, gID, tig);
        else         stage_write8i(stg0, acc[1], 0, mq - 1, nh, gID, tig);
        __syncthreads();
        copyout8i(out, z0 + 16, stg0, tid);
        // chunk 3 (mt 1, h2 2) -> stg1
        if (mq == 0) ch0_store8(out, z0 + 24, acc[1], 2, nh, gID, tig);
        else         stage_write8i(stg1, acc[1], 2, mq - 1, nh, gID, tig);
        __syncthreads();
        copyout8i(out, z0 + 24, stg1, tid);
    }
}

extern "C" void kernel_launch(void* const* d_in, const int* in_sizes, int n_in,
                              void* d_out, int out_size) {
    const float* x    = (const float*)d_in[0];
    const float* y    = (const float*)d_in[1];
    const float* tp_w = (const float*)d_in[2];
    const float* w0   = (const float*)d_in[3];
    const float* w1   = (const float*)d_in[4];
    float* out        = (float*)d_out;

    int Z = in_sizes[0] / 256;

    pack_kernel<<<(4096 + 64 + 255) / 256, 256>>>(tp_w, w0, w1);

    cudaFuncSetAttribute(tpmm_kernel,
                         cudaFuncAttributeMaxDynamicSharedMemorySize, DSM_BYTES);
    tpmm_kernel<<<Z / (TILE_Z * NITER), NTH, DSM_BYTES>>>(x, y, out);
}